// round 5
// baseline (speedup 1.0000x reference)
#include <cuda_runtime.h>
#include <cuda_bf16.h>

// ---------------------------------------------------------------------------
// NONLocalBlock2D: B=2, C=64, Ci=16, H=W=80, N=6400
// Round 5: 1 query/thread (low regs -> 3 CTAs/SM, 24 warps), key-split x4,
// ex2-domain softmax, packed f32x2 FMAs, split proj kernel.
// ---------------------------------------------------------------------------

#define Bb 2
#define Cc 64
#define CI 16
#define NN 6400
#define TQ 64           // queries per attn CTA (1 per thread)
#define KSPLIT 4
#define KLEN (NN / KSPLIT)   // 1600 keys per split
#define TK 160          // key tile
#define NTILE (KLEN / TK)    // 10
#define PHI_STRIDE 20   // floats; 80B rows, 16B aligned, conflict-free k..k+3
#define G_STRIDE   36   // floats; 144B rows, 16B aligned, conflict-free k..k+3
#define LOG2E 1.4426950408889634f

typedef unsigned long long u64;

#define FMA2(d, a, b, c) \
    asm("fma.rn.f32x2 %0, %1, %2, %3;" : "=l"(d) : "l"(a), "l"(b), "l"(c))
#define ADD2(d, a, b) \
    asm("add.rn.f32x2 %0, %1, %2;" : "=l"(d) : "l"(a), "l"(b))
#define PACK2(d, lo, hi) \
    asm("mov.b64 %0, {%1, %2};" : "=l"(d) : "r"(__float_as_uint(lo)), "r"(__float_as_uint(hi)))
#define UNPACK2(lo, hi, s) \
    { unsigned _ulo, _uhi; asm("mov.b64 {%0, %1}, %2;" : "=r"(_ulo), "=r"(_uhi) : "l"(s)); \
      lo = __uint_as_float(_ulo); hi = __uint_as_float(_uhi); }

__device__ __forceinline__ float ex2_approx(float v) {
    float r;
    asm("ex2.approx.f32 %0, %1;" : "=f"(r) : "f"(v));
    return r;
}

// Scratch (static device globals: no runtime allocation)
__device__ float d_theta[Bb * NN * CI];        // [b][n][ci], pre-scaled by log2e
__device__ float d_phi  [Bb * NN * CI];        // [b][n][ci]
__device__ float d_gv   [Bb * NN * 32];        // [b][n][0:16]=g_x, [16:32]=g_bf
__device__ float d_part [KSPLIT * Bb * NN * 36]; // per-split: 32 acc + sum at [32]

// ---------------------------------------------------------------------------
// Kernel 1: 1x1-conv projections. One thread per pixel per source tensor.
// gridDim.z = 2: z=0 -> bfimg side (theta, phi, g_bf); z=1 -> x side (g_x).
// ---------------------------------------------------------------------------
__global__ __launch_bounds__(256) void proj_kernel(
    const float* __restrict__ bfimg, const float* __restrict__ x,
    const float* __restrict__ w_theta, const float* __restrict__ b_theta,
    const float* __restrict__ w_phi,   const float* __restrict__ b_phi,
    const float* __restrict__ w_g,     const float* __restrict__ b_g,
    const float* __restrict__ w_gbf,   const float* __restrict__ b_gbf)
{
    __shared__ float sw[3][CI * Cc];
    __shared__ float sb[3][CI];

    int tid = threadIdx.x;
    int side = blockIdx.z;

    if (side == 0) {
        for (int i = tid; i < CI * Cc; i += 256) {
            sw[0][i] = w_theta[i];
            sw[1][i] = w_phi[i];
            sw[2][i] = w_gbf[i];
        }
        if (tid < CI) {
            sb[0][tid] = b_theta[tid];
            sb[1][tid] = b_phi[tid];
            sb[2][tid] = b_gbf[tid];
        }
    } else {
        for (int i = tid; i < CI * Cc; i += 256) sw[0][i] = w_g[i];
        if (tid < CI) sb[0][tid] = b_g[tid];
    }
    __syncthreads();

    int idx = blockIdx.x * 256 + tid;          // 0 .. 12799
    int b = idx / NN;
    int n = idx - b * NN;

    float v[Cc];
    if (side == 0) {
        const float* in0 = bfimg + (size_t)(b * Cc) * NN + n;
        #pragma unroll
        for (int c = 0; c < Cc; c++) v[c] = in0[(size_t)c * NN];

        #pragma unroll 1
        for (int ci = 0; ci < CI; ci++) {
            float a0 = sb[0][ci], a1 = sb[1][ci], a3 = sb[2][ci];
            #pragma unroll
            for (int c = 0; c < Cc; c++) {
                float t = v[c];
                a0 = fmaf(sw[0][ci * Cc + c], t, a0);
                a1 = fmaf(sw[1][ci * Cc + c], t, a1);
                a3 = fmaf(sw[2][ci * Cc + c], t, a3);
            }
            d_theta[(size_t)idx * CI + ci] = a0 * LOG2E;   // ex2 domain
            d_phi  [(size_t)idx * CI + ci] = a1;
            d_gv   [(size_t)idx * 32 + 16 + ci] = a3;      // g_bf upper half
        }
    } else {
        const float* in1 = x + (size_t)(b * Cc) * NN + n;
        #pragma unroll
        for (int c = 0; c < Cc; c++) v[c] = in1[(size_t)c * NN];

        #pragma unroll 1
        for (int ci = 0; ci < CI; ci++) {
            float a2 = sb[0][ci];
            #pragma unroll
            for (int c = 0; c < Cc; c++)
                a2 = fmaf(sw[0][ci * Cc + c], v[c], a2);
            d_gv[(size_t)idx * 32 + ci] = a2;              // g_x lower half
        }
    }
}

// ---------------------------------------------------------------------------
// Kernel 2: key-split attention. Grid (NN/TQ=100, B=2, KSPLIT=4) = 800 CTAs.
// 256 threads: q_local = tid>>2 (0..63), tsub = tid&3. One query per thread;
// keys k = j*4+tsub within each tile. Low regs -> 3 CTAs/SM.
// ---------------------------------------------------------------------------
__global__ __launch_bounds__(256, 3) void attn_kernel()
{
    __shared__ float s_phi[TK][PHI_STRIDE];   // 12800 B
    __shared__ float s_g  [TK][G_STRIDE];     // 23040 B

    int tid = threadIdx.x;
    int b = blockIdx.y;
    int split = blockIdx.z;
    int q_local = tid >> 2;
    int tsub = tid & 3;
    int q = blockIdx.x * TQ + q_local;

    // theta (log2 domain) -> 8 packed f32x2 registers
    u64 th2[8];
    {
        const float4* tp = (const float4*)(d_theta + ((size_t)b * NN + q) * CI);
        float4 t0 = tp[0], t1 = tp[1], t2 = tp[2], t3 = tp[3];
        PACK2(th2[0], t0.x, t0.y); PACK2(th2[1], t0.z, t0.w);
        PACK2(th2[2], t1.x, t1.y); PACK2(th2[3], t1.z, t1.w);
        PACK2(th2[4], t2.x, t2.y); PACK2(th2[5], t2.z, t2.w);
        PACK2(th2[6], t3.x, t3.y); PACK2(th2[7], t3.z, t3.w);
    }

    u64 acc2[16];
    #pragma unroll
    for (int i = 0; i < 16; i++) acc2[i] = 0ull;
    float sum_p = 0.f;

    const float* phi_base = d_phi + (size_t)b * NN * CI;
    const float* g_base   = d_gv  + (size_t)b * NN * 32;
    int kstart = split * KLEN;

    for (int t = 0; t < NTILE; t++) {
        int kbase = kstart + t * TK;
        __syncthreads();
        {
            const float4* src = (const float4*)(phi_base + (size_t)kbase * CI);
            #pragma unroll
            for (int i = tid; i < TK * 4; i += 256) {
                int key = i >> 2, c4 = i & 3;
                *(float4*)&s_phi[key][c4 * 4] = src[i];
            }
            const float4* gs = (const float4*)(g_base + (size_t)kbase * 32);
            #pragma unroll
            for (int i = tid; i < TK * 8; i += 256) {
                int key = i >> 3, c4 = i & 7;
                *(float4*)&s_g[key][c4 * 4] = gs[i];
            }
        }
        __syncthreads();

        #pragma unroll 4
        for (int j = 0; j < TK / 4; j++) {
            int k = j * 4 + tsub;
            const ulonglong2* pp = (const ulonglong2*)&s_phi[k][0];
            ulonglong2 p0 = pp[0], p1 = pp[1], p2v = pp[2], p3 = pp[3];

            u64 sA = 0ull, sB = 0ull;
            FMA2(sA, th2[0], p0.x, sA);  FMA2(sB, th2[1], p0.y, sB);
            FMA2(sA, th2[2], p1.x, sA);  FMA2(sB, th2[3], p1.y, sB);
            FMA2(sA, th2[4], p2v.x, sA); FMA2(sB, th2[5], p2v.y, sB);
            FMA2(sA, th2[6], p3.x, sA);  FMA2(sB, th2[7], p3.y, sB);
            ADD2(sA, sA, sB);
            float slo, shi;
            UNPACK2(slo, shi, sA);
            float p = ex2_approx(__fadd_rn(slo, shi));   // single MUFU
            sum_p += p;
            u64 pb;
            PACK2(pb, p, p);

            const ulonglong2* gg = (const ulonglong2*)&s_g[k][0];
            #pragma unroll
            for (int i = 0; i < 8; i++) {
                ulonglong2 gv = gg[i];
                FMA2(acc2[2 * i],     gv.x, pb, acc2[2 * i]);
                FMA2(acc2[2 * i + 1], gv.y, pb, acc2[2 * i + 1]);
            }
        }
    }

    // quad reduction (lanes xor 1, 2 share the query)
    const unsigned mask = 0xFFFFFFFFu;
    #pragma unroll
    for (int i = 0; i < 16; i++) {
        u64 o = __shfl_xor_sync(mask, acc2[i], 1); ADD2(acc2[i], acc2[i], o);
        o = __shfl_xor_sync(mask, acc2[i], 2);     ADD2(acc2[i], acc2[i], o);
    }
    sum_p += __shfl_xor_sync(mask, sum_p, 1);
    sum_p += __shfl_xor_sync(mask, sum_p, 2);

    // each lane writes its 8-channel slice (channels tsub*8 .. tsub*8+7)
    size_t base0 = (((size_t)split * Bb + b) * NN + q) * 36;
    {
        float lo0, hi0, lo1, hi1, lo2, hi2, lo3, hi3;
        int i0 = tsub * 4;
        UNPACK2(lo0, hi0, acc2[i0]);     UNPACK2(lo1, hi1, acc2[i0 + 1]);
        UNPACK2(lo2, hi2, acc2[i0 + 2]); UNPACK2(lo3, hi3, acc2[i0 + 3]);
        *(float4*)(d_part + base0 + tsub * 8)     = make_float4(lo0, hi0, lo1, hi1);
        *(float4*)(d_part + base0 + tsub * 8 + 4) = make_float4(lo2, hi2, lo3, hi3);
        if (tsub == 0) d_part[base0 + 32] = sum_p;
    }
}

// ---------------------------------------------------------------------------
// Kernel 3: combine splits, normalize, W/BN/residual epilogue.
// Grid (NN/64=100, B). 256 threads = 64 queries x 4 lanes.
// ---------------------------------------------------------------------------
__global__ __launch_bounds__(256) void combine_kernel(
    const float* __restrict__ bfimg, const float* __restrict__ x,
    const float* __restrict__ w_W,   const float* __restrict__ b_W,
    const float* __restrict__ bn_gamma, const float* __restrict__ bn_beta,
    const float* __restrict__ bn_mean,  const float* __restrict__ bn_var,
    float* __restrict__ out)
{
    __shared__ float s_w[Cc * CI];
    __shared__ float s_scale[Cc];
    __shared__ float s_bias[Cc];
    __shared__ float s_y[64][36];

    int tid = threadIdx.x;
    int b = blockIdx.y;
    int q_local = tid >> 2;
    int tsub = tid & 3;
    int q = blockIdx.x * 64 + q_local;

    for (int i = tid; i < Cc * CI; i += 256) s_w[i] = w_W[i];
    if (tid < Cc) {
        float sc = bn_gamma[tid] * rsqrtf(bn_var[tid] + 1e-5f);
        s_scale[tid] = sc;
        s_bias[tid] = (b_W[tid] - bn_mean[tid]) * sc + bn_beta[tid];
    }

    // sum this lane's 8 channels + sum_p over the 4 splits
    float y0 = 0.f, y1v = 0.f, y2v = 0.f, y3 = 0.f, y4 = 0.f, y5 = 0.f, y6 = 0.f, y7 = 0.f;
    float sp = 0.f;
    #pragma unroll
    for (int s = 0; s < KSPLIT; s++) {
        const float* p = d_part + (((size_t)s * Bb + b) * NN + q) * 36;
        float4 v0 = *(const float4*)(p + tsub * 8);
        float4 v1 = *(const float4*)(p + tsub * 8 + 4);
        y0 += v0.x; y1v += v0.y; y2v += v0.z; y3 += v0.w;
        y4 += v1.x; y5 += v1.y; y6 += v1.z; y7 += v1.w;
        sp += p[32];
    }
    float inv = 1.f / sp;
    int cb = tsub * 8;
    s_y[q_local][cb + 0] = y0 * inv;  s_y[q_local][cb + 1] = y1v * inv;
    s_y[q_local][cb + 2] = y2v * inv; s_y[q_local][cb + 3] = y3 * inv;
    s_y[q_local][cb + 4] = y4 * inv;  s_y[q_local][cb + 5] = y5 * inv;
    s_y[q_local][cb + 6] = y6 * inv;  s_y[q_local][cb + 7] = y7 * inv;
    __syncthreads();

    float ya[16], yb[16];
    #pragma unroll
    for (int i = 0; i < 16; i++) { ya[i] = s_y[q_local][i]; yb[i] = s_y[q_local][16 + i]; }

    int n = q;
    #pragma unroll 1
    for (int cc = 0; cc < 16; cc++) {
        int c = tsub * 16 + cc;
        float d1 = 0.f, d2 = 0.f;
        #pragma unroll
        for (int i = 0; i < 16; i++) {
            float w = s_w[c * CI + i];
            d1 = fmaf(w, ya[i], d1);
            d2 = fmaf(w, yb[i], d2);
        }
        float sc = s_scale[c], bi = s_bias[c];
        out[((size_t)(b * 128) + c) * NN + n] =
            fmaf(sc, d1, bi) + x[((size_t)(b * Cc) + c) * NN + n];
        out[((size_t)(b * 128) + 64 + c) * NN + n] =
            fmaf(sc, d2, bi) + bfimg[((size_t)(b * Cc) + c) * NN + n];
    }
}

// ---------------------------------------------------------------------------
extern "C" void kernel_launch(void* const* d_in, const int* in_sizes, int n_in,
                              void* d_out, int out_size)
{
    const float* bfimg   = (const float*)d_in[0];
    const float* x       = (const float*)d_in[1];
    const float* w_theta = (const float*)d_in[2];
    const float* b_theta = (const float*)d_in[3];
    const float* w_phi   = (const float*)d_in[4];
    const float* b_phi   = (const float*)d_in[5];
    const float* w_g     = (const float*)d_in[6];
    const float* b_g     = (const float*)d_in[7];
    const float* w_gbf   = (const float*)d_in[8];
    const float* b_gbf   = (const float*)d_in[9];
    const float* w_W     = (const float*)d_in[10];
    const float* b_W     = (const float*)d_in[11];
    const float* bn_gamma= (const float*)d_in[12];
    const float* bn_beta = (const float*)d_in[13];
    const float* bn_mean = (const float*)d_in[14];
    const float* bn_var  = (const float*)d_in[15];
    float* out = (float*)d_out;

    proj_kernel<<<dim3((Bb * NN) / 256, 1, 2), 256>>>(bfimg, x, w_theta, b_theta,
                                                      w_phi, b_phi, w_g, b_g,
                                                      w_gbf, b_gbf);
    attn_kernel<<<dim3(NN / TQ, Bb, KSPLIT), 256>>>();
    combine_kernel<<<dim3(NN / 64, Bb), 256>>>(bfimg, x, w_W, b_W,
                                               bn_gamma, bn_beta, bn_mean, bn_var, out);
}

// round 7
// speedup vs baseline: 2.0242x; 2.0242x over previous
#include <cuda_runtime.h>
#include <cuda_bf16.h>

// ---------------------------------------------------------------------------
// NONLocalBlock2D: B=2, C=64, Ci=16, H=W=80, N=6400
// Round 6: 4 queries/thread with channel-split quads (2 key-lanes x 2
// channel-halves), split score dot merged via shfl, key-split x4,
// ex2-domain softmax, packed f32x2 FMAs. 128-thread CTAs -> 3 CTAs/SM.
// ---------------------------------------------------------------------------

#define Bb 2
#define Cc 64
#define CI 16
#define NN 6400
#define TQ 128          // queries per attn CTA (4 per thread, 32 q-groups)
#define KSPLIT 4
#define KLEN (NN / KSPLIT)   // 1600 keys per split
#define TK 160          // key tile
#define NTILE (KLEN / TK)    // 10
#define PHI_STRIDE 20   // floats; 80B rows
#define G_STRIDE   36   // floats; 144B rows
#define LOG2E 1.4426950408889634f

typedef unsigned long long u64;

#define FMA2(d, a, b, c) \
    asm("fma.rn.f32x2 %0, %1, %2, %3;" : "=l"(d) : "l"(a), "l"(b), "l"(c))
#define ADD2(d, a, b) \
    asm("add.rn.f32x2 %0, %1, %2;" : "=l"(d) : "l"(a), "l"(b))
#define PACK2(d, lo, hi) \
    asm("mov.b64 %0, {%1, %2};" : "=l"(d) : "r"(__float_as_uint(lo)), "r"(__float_as_uint(hi)))
#define UNPACK2(lo, hi, s) \
    { unsigned _ulo, _uhi; asm("mov.b64 {%0, %1}, %2;" : "=r"(_ulo), "=r"(_uhi) : "l"(s)); \
      lo = __uint_as_float(_ulo); hi = __uint_as_float(_uhi); }

__device__ __forceinline__ float ex2_approx(float v) {
    float r;
    asm("ex2.approx.f32 %0, %1;" : "=f"(r) : "f"(v));
    return r;
}

// Scratch (static device globals: no runtime allocation)
__device__ float d_theta[Bb * NN * CI];        // [b][n][ci], pre-scaled by log2e
__device__ float d_phi  [Bb * NN * CI];        // [b][n][ci]
__device__ float d_gv   [Bb * NN * 32];        // [b][n][0:16]=g_x, [16:32]=g_bf
__device__ float d_part [KSPLIT * Bb * NN * 36]; // per-split: 32 acc + sum at [32]

// ---------------------------------------------------------------------------
// Kernel 1: 1x1-conv projections. One thread per pixel per source tensor.
// gridDim.z = 2: z=0 -> bfimg side (theta, phi, g_bf); z=1 -> x side (g_x).
// ---------------------------------------------------------------------------
__global__ __launch_bounds__(256) void proj_kernel(
    const float* __restrict__ bfimg, const float* __restrict__ x,
    const float* __restrict__ w_theta, const float* __restrict__ b_theta,
    const float* __restrict__ w_phi,   const float* __restrict__ b_phi,
    const float* __restrict__ w_g,     const float* __restrict__ b_g,
    const float* __restrict__ w_gbf,   const float* __restrict__ b_gbf)
{
    __shared__ float sw[3][CI * Cc];
    __shared__ float sb[3][CI];

    int tid = threadIdx.x;
    int side = blockIdx.z;

    if (side == 0) {
        for (int i = tid; i < CI * Cc; i += 256) {
            sw[0][i] = w_theta[i];
            sw[1][i] = w_phi[i];
            sw[2][i] = w_gbf[i];
        }
        if (tid < CI) {
            sb[0][tid] = b_theta[tid];
            sb[1][tid] = b_phi[tid];
            sb[2][tid] = b_gbf[tid];
        }
    } else {
        for (int i = tid; i < CI * Cc; i += 256) sw[0][i] = w_g[i];
        if (tid < CI) sb[0][tid] = b_g[tid];
    }
    __syncthreads();

    int idx = blockIdx.x * 256 + tid;          // 0 .. 12799
    int b = idx / NN;
    int n = idx - b * NN;

    float v[Cc];
    if (side == 0) {
        const float* in0 = bfimg + (size_t)(b * Cc) * NN + n;
        #pragma unroll
        for (int c = 0; c < Cc; c++) v[c] = in0[(size_t)c * NN];

        #pragma unroll 1
        for (int ci = 0; ci < CI; ci++) {
            float a0 = sb[0][ci], a1 = sb[1][ci], a3 = sb[2][ci];
            #pragma unroll
            for (int c = 0; c < Cc; c++) {
                float t = v[c];
                a0 = fmaf(sw[0][ci * Cc + c], t, a0);
                a1 = fmaf(sw[1][ci * Cc + c], t, a1);
                a3 = fmaf(sw[2][ci * Cc + c], t, a3);
            }
            d_theta[(size_t)idx * CI + ci] = a0 * LOG2E;   // ex2 domain
            d_phi  [(size_t)idx * CI + ci] = a1;
            d_gv   [(size_t)idx * 32 + 16 + ci] = a3;      // g_bf upper half
        }
    } else {
        const float* in1 = x + (size_t)(b * Cc) * NN + n;
        #pragma unroll
        for (int c = 0; c < Cc; c++) v[c] = in1[(size_t)c * NN];

        #pragma unroll 1
        for (int ci = 0; ci < CI; ci++) {
            float a2 = sb[0][ci];
            #pragma unroll
            for (int c = 0; c < Cc; c++)
                a2 = fmaf(sw[0][ci * Cc + c], v[c], a2);
            d_gv[(size_t)idx * 32 + ci] = a2;              // g_x lower half
        }
    }
}

// ---------------------------------------------------------------------------
// Kernel 2: key-split attention. Grid (NN/TQ=50, B=2, KSPLIT=4) = 400 CTAs,
// 128 threads, ~3 CTAs/SM. Quad layout: tsub = tid&3; klane = tsub&1 selects
// key parity, chalf = tsub>>1 selects channel half AND theta/phi half.
// Each thread: 4 queries (qg, qg+32, qg+64, qg+96), 16 value channels.
// Score dot split across chalf lanes, merged with one shfl.xor(2).
// Accumulators reduced across klane (shfl.xor(1)) at the end.
// ---------------------------------------------------------------------------
__global__ __launch_bounds__(128, 3) void attn_kernel()
{
    __shared__ float s_phi[TK][PHI_STRIDE];   // 12800 B
    __shared__ float s_g  [TK][G_STRIDE];     // 23040 B

    int tid = threadIdx.x;
    int b = blockIdx.y;
    int split = blockIdx.z;
    int qg = tid >> 2;            // 0..31
    int tsub = tid & 3;
    int klane = tsub & 1;
    int chalf = tsub >> 1;
    int qbase = blockIdx.x * TQ;

    // theta half-rows (log2 domain) for 4 queries -> 4 packed f32x2 each
    u64 th2[4][4];
    #pragma unroll
    for (int qi = 0; qi < 4; qi++) {
        int q = qbase + qg + qi * 32;
        const float4* tp = (const float4*)(d_theta + ((size_t)b * NN + q) * CI + chalf * 8);
        float4 t0 = tp[0], t1 = tp[1];
        PACK2(th2[qi][0], t0.x, t0.y); PACK2(th2[qi][1], t0.z, t0.w);
        PACK2(th2[qi][2], t1.x, t1.y); PACK2(th2[qi][3], t1.z, t1.w);
    }

    u64 acc2[4][8];               // 4 queries x 16 channels (8 f32x2)
    #pragma unroll
    for (int qi = 0; qi < 4; qi++)
        #pragma unroll
        for (int i = 0; i < 8; i++) acc2[qi][i] = 0ull;
    float sum_p[4] = {0.f, 0.f, 0.f, 0.f};

    const float* phi_base = d_phi + (size_t)b * NN * CI;
    const float* g_base   = d_gv  + (size_t)b * NN * 32;
    int kstart = split * KLEN;
    const unsigned mask = 0xFFFFFFFFu;

    for (int t = 0; t < NTILE; t++) {
        int kbase = kstart + t * TK;
        __syncthreads();
        {
            const float4* src = (const float4*)(phi_base + (size_t)kbase * CI);
            #pragma unroll
            for (int i = tid; i < TK * 4; i += 128) {
                int key = i >> 2, c4 = i & 3;
                *(float4*)&s_phi[key][c4 * 4] = src[i];
            }
            const float4* gs = (const float4*)(g_base + (size_t)kbase * 32);
            #pragma unroll
            for (int i = tid; i < TK * 8; i += 128) {
                int key = i >> 3, c4 = i & 7;
                *(float4*)&s_g[key][c4 * 4] = gs[i];
            }
        }
        __syncthreads();

        #pragma unroll 2
        for (int j = 0; j < TK / 2; j++) {
            int k = j * 2 + klane;
            // phi half-row: 8 floats at s_phi[k][chalf*8]
            const ulonglong2* pp = (const ulonglong2*)&s_phi[k][chalf * 8];
            ulonglong2 pa = pp[0], pb = pp[1];
            // g half-row: 16 floats at s_g[k][chalf*16]
            const ulonglong2* gg = (const ulonglong2*)&s_g[k][chalf * 16];
            ulonglong2 g0 = gg[0], g1 = gg[1], g2 = gg[2], g3 = gg[3];

            float part[4];
            #pragma unroll
            for (int qi = 0; qi < 4; qi++) {
                u64 sA = 0ull, sB = 0ull;
                FMA2(sA, th2[qi][0], pa.x, sA);
                FMA2(sB, th2[qi][1], pa.y, sB);
                FMA2(sA, th2[qi][2], pb.x, sA);
                FMA2(sB, th2[qi][3], pb.y, sB);
                ADD2(sA, sA, sB);
                float lo, hi;
                UNPACK2(lo, hi, sA);
                part[qi] = __fadd_rn(lo, hi);
            }
            #pragma unroll
            for (int qi = 0; qi < 4; qi++) {
                float other = __shfl_xor_sync(mask, part[qi], 2);
                float p = ex2_approx(__fadd_rn(part[qi], other));
                sum_p[qi] += p;
                u64 p2;
                PACK2(p2, p, p);
                FMA2(acc2[qi][0], g0.x, p2, acc2[qi][0]);
                FMA2(acc2[qi][1], g0.y, p2, acc2[qi][1]);
                FMA2(acc2[qi][2], g1.x, p2, acc2[qi][2]);
                FMA2(acc2[qi][3], g1.y, p2, acc2[qi][3]);
                FMA2(acc2[qi][4], g2.x, p2, acc2[qi][4]);
                FMA2(acc2[qi][5], g2.y, p2, acc2[qi][5]);
                FMA2(acc2[qi][6], g3.x, p2, acc2[qi][6]);
                FMA2(acc2[qi][7], g3.y, p2, acc2[qi][7]);
            }
        }
    }

    // reduce over the two key-lanes (xor 1); channel halves stay separate
    #pragma unroll
    for (int qi = 0; qi < 4; qi++) {
        #pragma unroll
        for (int i = 0; i < 8; i++) {
            u64 o = __shfl_xor_sync(mask, acc2[qi][i], 1);
            ADD2(acc2[qi][i], acc2[qi][i], o);
        }
        sum_p[qi] += __shfl_xor_sync(mask, sum_p[qi], 1);
    }

    // klane 0 writes: 16 channels (chalf half) per query + sum
    if (klane == 0) {
        #pragma unroll
        for (int qi = 0; qi < 4; qi++) {
            int q = qbase + qg + qi * 32;
            size_t base = (((size_t)split * Bb + b) * NN + q) * 36 + chalf * 16;
            float lo0, hi0, lo1, hi1;
            UNPACK2(lo0, hi0, acc2[qi][0]); UNPACK2(lo1, hi1, acc2[qi][1]);
            *(float4*)(d_part + base)     = make_float4(lo0, hi0, lo1, hi1);
            UNPACK2(lo0, hi0, acc2[qi][2]); UNPACK2(lo1, hi1, acc2[qi][3]);
            *(float4*)(d_part + base + 4) = make_float4(lo0, hi0, lo1, hi1);
            UNPACK2(lo0, hi0, acc2[qi][4]); UNPACK2(lo1, hi1, acc2[qi][5]);
            *(float4*)(d_part + base + 8) = make_float4(lo0, hi0, lo1, hi1);
            UNPACK2(lo0, hi0, acc2[qi][6]); UNPACK2(lo1, hi1, acc2[qi][7]);
            *(float4*)(d_part + base + 12) = make_float4(lo0, hi0, lo1, hi1);
            if (chalf == 0)
                d_part[(((size_t)split * Bb + b) * NN + q) * 36 + 32] = sum_p[qi];
        }
    }
}

// ---------------------------------------------------------------------------
// Kernel 3: combine splits, normalize, W/BN/residual epilogue.
// Grid (NN/64=100, B). 256 threads = 64 queries x 4 lanes.
// ---------------------------------------------------------------------------
__global__ __launch_bounds__(256) void combine_kernel(
    const float* __restrict__ bfimg, const float* __restrict__ x,
    const float* __restrict__ w_W,   const float* __restrict__ b_W,
    const float* __restrict__ bn_gamma, const float* __restrict__ bn_beta,
    const float* __restrict__ bn_mean,  const float* __restrict__ bn_var,
    float* __restrict__ out)
{
    __shared__ float s_w[Cc * CI];
    __shared__ float s_scale[Cc];
    __shared__ float s_bias[Cc];
    __shared__ float s_y[64][36];

    int tid = threadIdx.x;
    int b = blockIdx.y;
    int q_local = tid >> 2;
    int tsub = tid & 3;
    int q = blockIdx.x * 64 + q_local;

    for (int i = tid; i < Cc * CI; i += 256) s_w[i] = w_W[i];
    if (tid < Cc) {
        float sc = bn_gamma[tid] * rsqrtf(bn_var[tid] + 1e-5f);
        s_scale[tid] = sc;
        s_bias[tid] = (b_W[tid] - bn_mean[tid]) * sc + bn_beta[tid];
    }

    // sum this lane's 8 channels + sum_p over the splits
    float y0 = 0.f, y1v = 0.f, y2v = 0.f, y3 = 0.f, y4 = 0.f, y5 = 0.f, y6 = 0.f, y7 = 0.f;
    float sp = 0.f;
    #pragma unroll
    for (int s = 0; s < KSPLIT; s++) {
        const float* p = d_part + (((size_t)s * Bb + b) * NN + q) * 36;
        float4 v0 = *(const float4*)(p + tsub * 8);
        float4 v1 = *(const float4*)(p + tsub * 8 + 4);
        y0 += v0.x; y1v += v0.y; y2v += v0.z; y3 += v0.w;
        y4 += v1.x; y5 += v1.y; y6 += v1.z; y7 += v1.w;
        sp += p[32];
    }
    float inv = 1.f / sp;
    int cb = tsub * 8;
    s_y[q_local][cb + 0] = y0 * inv;  s_y[q_local][cb + 1] = y1v * inv;
    s_y[q_local][cb + 2] = y2v * inv; s_y[q_local][cb + 3] = y3 * inv;
    s_y[q_local][cb + 4] = y4 * inv;  s_y[q_local][cb + 5] = y5 * inv;
    s_y[q_local][cb + 6] = y6 * inv;  s_y[q_local][cb + 7] = y7 * inv;
    __syncthreads();

    float ya[16], yb[16];
    #pragma unroll
    for (int i = 0; i < 16; i++) { ya[i] = s_y[q_local][i]; yb[i] = s_y[q_local][16 + i]; }

    int n = q;
    #pragma unroll 1
    for (int cc = 0; cc < 16; cc++) {
        int c = tsub * 16 + cc;
        float d1 = 0.f, d2 = 0.f;
        #pragma unroll
        for (int i = 0; i < 16; i++) {
            float w = s_w[c * CI + i];
            d1 = fmaf(w, ya[i], d1);
            d2 = fmaf(w, yb[i], d2);
        }
        float sc = s_scale[c], bi = s_bias[c];
        out[((size_t)(b * 128) + c) * NN + n] =
            fmaf(sc, d1, bi) + x[((size_t)(b * Cc) + c) * NN + n];
        out[((size_t)(b * 128) + 64 + c) * NN + n] =
            fmaf(sc, d2, bi) + bfimg[((size_t)(b * Cc) + c) * NN + n];
    }
}

// ---------------------------------------------------------------------------
extern "C" void kernel_launch(void* const* d_in, const int* in_sizes, int n_in,
                              void* d_out, int out_size)
{
    const float* bfimg   = (const float*)d_in[0];
    const float* x       = (const float*)d_in[1];
    const float* w_theta = (const float*)d_in[2];
    const float* b_theta = (const float*)d_in[3];
    const float* w_phi   = (const float*)d_in[4];
    const float* b_phi   = (const float*)d_in[5];
    const float* w_g     = (const float*)d_in[6];
    const float* b_g     = (const float*)d_in[7];
    const float* w_gbf   = (const float*)d_in[8];
    const float* b_gbf   = (const float*)d_in[9];
    const float* w_W     = (const float*)d_in[10];
    const float* b_W     = (const float*)d_in[11];
    const float* bn_gamma= (const float*)d_in[12];
    const float* bn_beta = (const float*)d_in[13];
    const float* bn_mean = (const float*)d_in[14];
    const float* bn_var  = (const float*)d_in[15];
    float* out = (float*)d_out;

    proj_kernel<<<dim3((Bb * NN) / 256, 1, 2), 256>>>(bfimg, x, w_theta, b_theta,
                                                      w_phi, b_phi, w_g, b_g,
                                                      w_gbf, b_gbf);
    attn_kernel<<<dim3(NN / TQ, Bb, KSPLIT), 128>>>();
    combine_kernel<<<dim3(NN / 64, Bb), 256>>>(bfimg, x, w_W, b_W,
                                               bn_gamma, bn_beta, bn_mean, bn_var, out);
}

// round 9
// speedup vs baseline: 7.4749x; 3.6927x over previous
#include <cuda_runtime.h>
#include <cuda_bf16.h>
#include <cstdint>

// ---------------------------------------------------------------------------
// NONLocalBlock2D: B=2, C=64, Ci=16, H=W=80, N=6400
// Round 8: warp-level HMMA (mma.sync m16n8k16 bf16) flash attention.
//   proj    -> bf16 theta (log2e folded) [q][ch], bf16 phi [key][ch],
//              bf16 g transposed [ch][key]
//   attn    -> per warp: 16 queries. Per 128-key tile:
//                MMA1 S = theta @ phi^T (16 MMAs), exp in regs,
//                C-frag -> A-frag repack (no SMEM for P),
//                MMA2 O += P @ g^T (32 MMAs). Row sums in regs.
//              unnormalized (O, sum) -> d_part. KSPLIT=3 -> 600 CTAs.
//   combine -> reduce splits, normalize, W/BN/residual epilogue (fp32)
// ---------------------------------------------------------------------------

#define Bb 2
#define Cc 64
#define CI 16
#define NN 6400
#define KSPLIT 3
#define LOG2E 1.4426950408889634f

#define PHI_PITCH 48     // bytes/row (12 floats): bank-mult 12 -> conflict-free
#define G_PITCH   304    // bytes/row (76 floats): 76 mod 32 = 12 -> conflict-free

__device__ __forceinline__ float ex2_approx(float v) {
    float r;
    asm("ex2.approx.f32 %0, %1;" : "=f"(r) : "f"(v));
    return r;
}
__device__ __forceinline__ uint32_t pack_bf16(float lo, float hi) {
    uint32_t r;
    asm("cvt.rn.bf16x2.f32 %0, %1, %2;" : "=r"(r) : "f"(hi), "f"(lo));
    return r;
}
__device__ __forceinline__ void mma16816(float c[4], const uint32_t a[4],
                                         uint32_t b0, uint32_t b1) {
    asm volatile(
        "mma.sync.aligned.m16n8k16.row.col.f32.bf16.bf16.f32 "
        "{%0,%1,%2,%3}, {%4,%5,%6,%7}, {%8,%9}, {%0,%1,%2,%3};"
        : "+f"(c[0]), "+f"(c[1]), "+f"(c[2]), "+f"(c[3])
        : "r"(a[0]), "r"(a[1]), "r"(a[2]), "r"(a[3]), "r"(b0), "r"(b1));
}

// Scratch (static device globals: no runtime allocation)
__device__ __align__(256) unsigned int   d_thetab[Bb * NN * 8];   // bf16x2 pairs, log2e folded
__device__ __align__(256) unsigned int   d_phib  [Bb * NN * 8];   // bf16x2 pairs
__device__ __align__(256) __nv_bfloat16  d_gvt   [Bb * 32 * NN];  // [b][ch][n]; 0:16 g_x, 16:32 g_bf
__device__ __align__(256) float          d_part  [KSPLIT * Bb * NN * 36];

// ---------------------------------------------------------------------------
// Kernel 1: projections -> bf16 scratch. gridDim.z=2: z=0 bfimg side, z=1 x side.
// ---------------------------------------------------------------------------
__global__ __launch_bounds__(256) void proj_kernel(
    const float* __restrict__ bfimg, const float* __restrict__ x,
    const float* __restrict__ w_theta, const float* __restrict__ b_theta,
    const float* __restrict__ w_phi,   const float* __restrict__ b_phi,
    const float* __restrict__ w_g,     const float* __restrict__ b_g,
    const float* __restrict__ w_gbf,   const float* __restrict__ b_gbf)
{
    __shared__ float sw[3][CI * Cc];
    __shared__ float sb[3][CI];

    int tid = threadIdx.x;
    int side = blockIdx.z;

    if (side == 0) {
        for (int i = tid; i < CI * Cc; i += 256) {
            sw[0][i] = w_theta[i];
            sw[1][i] = w_phi[i];
            sw[2][i] = w_gbf[i];
        }
        if (tid < CI) { sb[0][tid] = b_theta[tid]; sb[1][tid] = b_phi[tid]; sb[2][tid] = b_gbf[tid]; }
    } else {
        for (int i = tid; i < CI * Cc; i += 256) sw[0][i] = w_g[i];
        if (tid < CI) sb[0][tid] = b_g[tid];
    }
    __syncthreads();

    int idx = blockIdx.x * 256 + tid;          // 0 .. 12799
    int b = idx / NN;
    int n = idx - b * NN;

    float v[Cc];
    if (side == 0) {
        const float* in0 = bfimg + (size_t)(b * Cc) * NN + n;
        #pragma unroll
        for (int c = 0; c < Cc; c++) v[c] = in0[(size_t)c * NN];

        float th[CI], ph[CI];
        #pragma unroll 1
        for (int ci = 0; ci < CI; ci++) {
            float a0 = sb[0][ci], a1 = sb[1][ci], a3 = sb[2][ci];
            #pragma unroll
            for (int c = 0; c < Cc; c++) {
                float t = v[c];
                a0 = fmaf(sw[0][ci * Cc + c], t, a0);
                a1 = fmaf(sw[1][ci * Cc + c], t, a1);
                a3 = fmaf(sw[2][ci * Cc + c], t, a3);
            }
            th[ci] = a0 * LOG2E;
            ph[ci] = a1;
            d_gvt[(size_t)(b * 32 + 16 + ci) * NN + n] = __float2bfloat16(a3);
        }
        unsigned int tp[8], pp[8];
        #pragma unroll
        for (int j = 0; j < 8; j++) {
            tp[j] = pack_bf16(th[2 * j], th[2 * j + 1]);
            pp[j] = pack_bf16(ph[2 * j], ph[2 * j + 1]);
        }
        *(uint4*)&d_thetab[(size_t)idx * 8]     = make_uint4(tp[0], tp[1], tp[2], tp[3]);
        *(uint4*)&d_thetab[(size_t)idx * 8 + 4] = make_uint4(tp[4], tp[5], tp[6], tp[7]);
        *(uint4*)&d_phib[(size_t)idx * 8]       = make_uint4(pp[0], pp[1], pp[2], pp[3]);
        *(uint4*)&d_phib[(size_t)idx * 8 + 4]   = make_uint4(pp[4], pp[5], pp[6], pp[7]);
    } else {
        const float* in1 = x + (size_t)(b * Cc) * NN + n;
        #pragma unroll
        for (int c = 0; c < Cc; c++) v[c] = in1[(size_t)c * NN];

        #pragma unroll 1
        for (int ci = 0; ci < CI; ci++) {
            float a2 = sb[0][ci];
            #pragma unroll
            for (int c = 0; c < Cc; c++)
                a2 = fmaf(sw[0][ci * Cc + c], v[c], a2);
            d_gvt[(size_t)(b * 32 + ci) * NN + n] = __float2bfloat16(a2);
        }
    }
}

// ---------------------------------------------------------------------------
// Kernel 2: HMMA flash attention. Grid (NN/64=100, Bb, KSPLIT) = 600 CTAs,
// 128 threads = 4 warps x 16 queries. Splits: 17/17/16 tiles of 128 keys.
// ---------------------------------------------------------------------------
__global__ __launch_bounds__(128) void attn_kernel()
{
    __shared__ __align__(16) char s_phi[128 * PHI_PITCH];  // 6144 B
    __shared__ __align__(16) char s_g[32 * G_PITCH];       // 9728 B

    int tid = threadIdx.x;
    int wid = tid >> 5, lane = tid & 31;
    int g = lane >> 2, t = lane & 3;
    int b = blockIdx.y, split = blockIdx.z;
    int qbase = blockIdx.x * 64;
    int kstart = split * 2176;
    int ntiles = (split < 2) ? 17 : 16;

    int q0 = qbase + wid * 16 + g;             // rows g and g+8 of this warp's M=16

    // theta A-fragment (constant for whole kernel)
    uint32_t a_th[4];
    {
        const unsigned int* th0 = d_thetab + ((size_t)b * NN + q0) * 8;
        const unsigned int* th1 = th0 + 8 * 8;       // q0 + 8
        a_th[0] = th0[t];     a_th[1] = th1[t];
        a_th[2] = th0[t + 4]; a_th[3] = th1[t + 4];
    }

    float o[4][4];
    #pragma unroll
    for (int nb = 0; nb < 4; nb++)
        #pragma unroll
        for (int i = 0; i < 4; i++) o[nb][i] = 0.f;
    float sumA = 0.f, sumB = 0.f;

    for (int tt = 0; tt < ntiles; tt++) {
        int kbase = kstart + tt * 128;
        __syncthreads();
        // phi tile: 128 keys x 32B -> rows of PHI_PITCH
        {
            const float4* src = (const float4*)(d_phib + ((size_t)b * NN + kbase) * 8);
            #pragma unroll
            for (int i = tid; i < 256; i += 128) {
                int key = i >> 1, h = i & 1;
                *(float4*)(s_phi + key * PHI_PITCH + h * 16) = src[i];
            }
        }
        // g tile: 32 ch x 128 keys (256B) -> rows of G_PITCH
        {
            #pragma unroll
            for (int i = tid; i < 512; i += 128) {
                int ch = i >> 4, seg = i & 15;
                const float4* src = (const float4*)(d_gvt + (size_t)(b * 32 + ch) * NN + kbase + seg * 8);
                *(float4*)(s_g + ch * G_PITCH + seg * 16) = src[0];
            }
        }
        __syncthreads();

        #pragma unroll 2
        for (int kk = 0; kk < 8; kk++) {
            // MMA1: two S tiles (keys 16kk .. 16kk+15)
            float s0[4] = {0.f, 0.f, 0.f, 0.f};
            float s1[4] = {0.f, 0.f, 0.f, 0.f};
            {
                const char* r0 = s_phi + (16 * kk + g) * PHI_PITCH + 4 * t;
                mma16816(s0, a_th, *(const uint32_t*)r0, *(const uint32_t*)(r0 + 16));
                const char* r1 = r0 + 8 * PHI_PITCH;
                mma16816(s1, a_th, *(const uint32_t*)r1, *(const uint32_t*)(r1 + 16));
            }
            // exp (ex2; theta pre-scaled by log2e)
            #pragma unroll
            for (int i = 0; i < 4; i++) {
                s0[i] = ex2_approx(s0[i]);
                s1[i] = ex2_approx(s1[i]);
            }
            sumA += (s0[0] + s0[1]) + (s1[0] + s1[1]);
            sumB += (s0[2] + s0[3]) + (s1[2] + s1[3]);
            // C-frag -> A-frag repack (P, K=16 keys)
            uint32_t a_p[4];
            a_p[0] = pack_bf16(s0[0], s0[1]);
            a_p[1] = pack_bf16(s0[2], s0[3]);
            a_p[2] = pack_bf16(s1[0], s1[1]);
            a_p[3] = pack_bf16(s1[2], s1[3]);
            // MMA2: O += P @ g^T over 4 channel blocks
            const char* gb = s_g + g * G_PITCH + 32 * kk + 4 * t;
            #pragma unroll
            for (int nb = 0; nb < 4; nb++) {
                const char* r = gb + nb * 8 * G_PITCH;
                mma16816(o[nb], a_p, *(const uint32_t*)r, *(const uint32_t*)(r + 16));
            }
        }
    }

    // row sums: reduce over the quad (t)
    sumA += __shfl_xor_sync(0xFFFFFFFFu, sumA, 1);
    sumA += __shfl_xor_sync(0xFFFFFFFFu, sumA, 2);
    sumB += __shfl_xor_sync(0xFFFFFFFFu, sumB, 1);
    sumB += __shfl_xor_sync(0xFFFFFFFFu, sumB, 2);

    // write unnormalized partials
    {
        size_t base0 = (((size_t)split * Bb + b) * NN + q0) * 36;
        size_t base1 = base0 + 8 * 36;       // q0 + 8
        #pragma unroll
        for (int nb = 0; nb < 4; nb++) {
            int ch = 8 * nb + 2 * t;
            *(float2*)(d_part + base0 + ch) = make_float2(o[nb][0], o[nb][1]);
            *(float2*)(d_part + base1 + ch) = make_float2(o[nb][2], o[nb][3]);
        }
        if (t == 0) {
            d_part[base0 + 32] = sumA;
            d_part[base1 + 32] = sumB;
        }
    }
}

// ---------------------------------------------------------------------------
// Kernel 3: combine splits, normalize, W/BN/residual epilogue. fp32.
// ---------------------------------------------------------------------------
__global__ __launch_bounds__(256) void combine_kernel(
    const float* __restrict__ bfimg, const float* __restrict__ x,
    const float* __restrict__ w_W,   const float* __restrict__ b_W,
    const float* __restrict__ bn_gamma, const float* __restrict__ bn_beta,
    const float* __restrict__ bn_mean,  const float* __restrict__ bn_var,
    float* __restrict__ out)
{
    __shared__ float s_w[Cc * CI];
    __shared__ float s_scale[Cc];
    __shared__ float s_bias[Cc];
    __shared__ float s_y[64][36];

    int tid = threadIdx.x;
    int b = blockIdx.y;
    int q_local = tid >> 2;
    int tsub = tid & 3;
    int q = blockIdx.x * 64 + q_local;

    for (int i = tid; i < Cc * CI; i += 256) s_w[i] = w_W[i];
    if (tid < Cc) {
        float sc = bn_gamma[tid] * rsqrtf(bn_var[tid] + 1e-5f);
        s_scale[tid] = sc;
        s_bias[tid] = (b_W[tid] - bn_mean[tid]) * sc + bn_beta[tid];
    }

    float y0 = 0.f, y1v = 0.f, y2v = 0.f, y3 = 0.f, y4 = 0.f, y5 = 0.f, y6 = 0.f, y7 = 0.f;
    float sp = 0.f;
    #pragma unroll
    for (int s = 0; s < KSPLIT; s++) {
        const float* p = d_part + (((size_t)s * Bb + b) * NN + q) * 36;
        float4 v0 = *(const float4*)(p + tsub * 8);
        float4 v1 = *(const float4*)(p + tsub * 8 + 4);
        y0 += v0.x; y1v += v0.y; y2v += v0.z; y3 += v0.w;
        y4 += v1.x; y5 += v1.y; y6 += v1.z; y7 += v1.w;
        sp += p[32];
    }
    float inv = 1.f / sp;
    int cb = tsub * 8;
    s_y[q_local][cb + 0] = y0 * inv;  s_y[q_local][cb + 1] = y1v * inv;
    s_y[q_local][cb + 2] = y2v * inv; s_y[q_local][cb + 3] = y3 * inv;
    s_y[q_local][cb + 4] = y4 * inv;  s_y[q_local][cb + 5] = y5 * inv;
    s_y[q_local][cb + 6] = y6 * inv;  s_y[q_local][cb + 7] = y7 * inv;
    __syncthreads();

    float ya[16], yb[16];
    #pragma unroll
    for (int i = 0; i < 16; i++) { ya[i] = s_y[q_local][i]; yb[i] = s_y[q_local][16 + i]; }

    int n = q;
    #pragma unroll 1
    for (int cc = 0; cc < 16; cc++) {
        int c = tsub * 16 + cc;
        float d1 = 0.f, d2 = 0.f;
        #pragma unroll
        for (int i = 0; i < 16; i++) {
            float w = s_w[c * CI + i];
            d1 = fmaf(w, ya[i], d1);
            d2 = fmaf(w, yb[i], d2);
        }
        float sc = s_scale[c], bi = s_bias[c];
        out[((size_t)(b * 128) + c) * NN + n] =
            fmaf(sc, d1, bi) + x[((size_t)(b * Cc) + c) * NN + n];
        out[((size_t)(b * 128) + 64 + c) * NN + n] =
            fmaf(sc, d2, bi) + bfimg[((size_t)(b * Cc) + c) * NN + n];
    }
}

// ---------------------------------------------------------------------------
extern "C" void kernel_launch(void* const* d_in, const int* in_sizes, int n_in,
                              void* d_out, int out_size)
{
    const float* bfimg   = (const float*)d_in[0];
    const float* x       = (const float*)d_in[1];
    const float* w_theta = (const float*)d_in[2];
    const float* b_theta = (const float*)d_in[3];
    const float* w_phi   = (const float*)d_in[4];
    const float* b_phi   = (const float*)d_in[5];
    const float* w_g     = (const float*)d_in[6];
    const float* b_g     = (const float*)d_in[7];
    const float* w_gbf   = (const float*)d_in[8];
    const float* b_gbf   = (const float*)d_in[9];
    const float* w_W     = (const float*)d_in[10];
    const float* b_W     = (const float*)d_in[11];
    const float* bn_gamma= (const float*)d_in[12];
    const float* bn_beta = (const float*)d_in[13];
    const float* bn_mean = (const float*)d_in[14];
    const float* bn_var  = (const float*)d_in[15];
    float* out = (float*)d_out;

    proj_kernel<<<dim3((Bb * NN) / 256, 1, 2), 256>>>(bfimg, x, w_theta, b_theta,
                                                      w_phi, b_phi, w_g, b_g,
                                                      w_gbf, b_gbf);
    attn_kernel<<<dim3(NN / 64, Bb, KSPLIT), 128>>>();
    combine_kernel<<<dim3(NN / 64, Bb), 256>>>(bfimg, x, w_W, b_W,
                                               bn_gamma, bn_beta, bn_mean, bn_var, out);
}